// round 12
// baseline (speedup 1.0000x reference)
#include <cuda_runtime.h>
#include <cstdint>

// FWHT N=4096 fp32 — TWO rows per CTA with cp.async prefetch overlap.
// Row A: loaded via LDG (as in best R8 kernel), computed, stored.
// Row B: prefetched into smem buf1 by cp.async.cg DURING row A's compute,
//        then computed out of smem. Keeps DRAM reads flowing through the
//        CTA's otherwise DRAM-silent compute phases; 12 rows in flight/SM.
//
// Per row: 12 stages, 3 register rounds (proven R5/R8 bit mapping):
//   round 1: bits {0,1,7,8}   (LDG.128 row A / linear LDS.128 row B)
//   round 2: bits {2,3,4,5}   swizzled smem exchange
//   round 3: bits {6,9,10,11} swizzled read; coalesced scalar STG (__stcs)
// XOR swizzle on float4 slots: s' = s ^ ((s>>4)&7) — conflict-free everywhere.
// Output scaled by 2^-6 (normalized Hadamard).

#define HN       4096
#define NTHREADS 256
#define RPT      16
#define NSLOTS   (HN / 4)        // 1024 float4 slots per row

__device__ __forceinline__ void cp_async16(uint32_t saddr, const void* gptr) {
    asm volatile("cp.async.cg.shared.global [%0], [%1], 16;"
                 :: "r"(saddr), "l"(gptr) : "memory");
}

#define BUTTERFLY_ALL()                                   \
    _Pragma("unroll")                                     \
    for (int st = 1; st < RPT; st <<= 1) {                \
        _Pragma("unroll")                                 \
        for (int i = 0; i < RPT; i++) {                   \
            if (!(i & st)) {                              \
                float a = v[i], b = v[i ^ st];            \
                v[i] = a + b;  v[i ^ st] = a - b;         \
            }                                             \
        }                                                 \
    }

__global__ __launch_bounds__(NTHREADS, 6)
void fwht2r_kernel(const float* __restrict__ X, float* __restrict__ Y)
{
    __shared__ float4 buf0[NSLOTS];            // 16 KB working buffer
    __shared__ float4 buf1[NSLOTS];            // 16 KB prefetch buffer
    float* const sf = reinterpret_cast<float*>(buf0);

    const size_t rp = blockIdx.x;              // row pair
    const float* __restrict__ x0 = X + rp * (2 * HN);
    const float* __restrict__ x1 = x0 + HN;
    float*       __restrict__ y0 = Y + rp * (2 * HN);
    float*       __restrict__ y1 = y0 + HN;

    const int t = threadIdx.x;
    const int w = t >> 5;
    const int l = t & 31;

    // round-2/3 constants (thread-invariant across both rows)
    const int p  = l & 3;
    const int q  = (l >> 2) & 1;
    const int u  = (l >> 3) & 3;
    const int sbase = 16 * q + 32 * u + 128 * w;
    const int sig   = q + 2 * u;
    const int u2 = w >> 1;
    const int m  = ((w & 1) << 5) | l;
    const int mq = m >> 2;
    const int mp = m & 3;
    const int obase = m + 128 * u2;

    // ---- kick off row-B prefetch immediately (streams during row-A work) ----
    {
        const uint32_t sb1 = (uint32_t)__cvta_generic_to_shared(buf1);
        const float4* __restrict__ xv1 = reinterpret_cast<const float4*>(x1);
        #pragma unroll
        for (int k = 0; k < 4; k++) {
            int slot = k * 256 + t;            // lane-contiguous per k
            cp_async16(sb1 + (uint32_t)slot * 16u, xv1 + slot);
        }
        asm volatile("cp.async.commit_group;" ::: "memory");
    }

    float v[RPT];

    // ================= ROW A =================
    // Round 1: lane-contiguous LDG.128; reg r=j*4+k -> bits {0,1}=r0r1, {7,8}=r2r3
    {
        const float4* __restrict__ xv0 = reinterpret_cast<const float4*>(x0);
        #pragma unroll
        for (int j = 0; j < 4; j++) {
            float4 a = xv0[w * 128 + j * 32 + l];
            v[4*j+0] = a.x; v[4*j+1] = a.y; v[4*j+2] = a.z; v[4*j+3] = a.w;
        }
    }
    BUTTERFLY_ALL();

    // Exchange 1: swizzled float4 write into buf0
    #pragma unroll
    for (int j = 0; j < 4; j++) {
        int s  = w * 128 + j * 32 + l;
        buf0[s ^ ((s >> 4) & 7)] =
            make_float4(v[4*j+0], v[4*j+1], v[4*j+2], v[4*j+3]);
    }
    __syncthreads();

    // Round 2: bits {2,3,4,5}
    #pragma unroll
    for (int i = 0; i < RPT; i++) v[i] = sf[((sbase + i) ^ sig) * 4 + p];
    BUTTERFLY_ALL();
    #pragma unroll
    for (int i = 0; i < RPT; i++) sf[((sbase + i) ^ sig) * 4 + p] = v[i];
    __syncthreads();

    // Round 3: bits {6,9,10,11}; store row A
    #pragma unroll
    for (int i2 = 0; i2 < RPT; i2++) {
        int b6 = i2 & 1, hi = i2 >> 1;
        int s  = mq + 16 * b6 + 32 * u2 + 128 * hi;
        v[i2] = sf[(s ^ (b6 + 2 * u2)) * 4 + mp];
    }
    BUTTERFLY_ALL();
    #pragma unroll
    for (int i2 = 0; i2 < RPT; i2++) {
        int b6 = i2 & 1, hi = i2 >> 1;
        __stcs(&y0[obase + 64 * b6 + 512 * hi], v[i2] * 0.015625f);
    }

    // ================= ROW B =================
    asm volatile("cp.async.wait_group 0;" ::: "memory");
    __syncthreads();   // buf1 ready; also: all row-A reads of buf0 complete

    // Round 1: linear LDS.128 from buf1 (slot = w*128+j*32+l, conflict-free)
    #pragma unroll
    for (int j = 0; j < 4; j++) {
        float4 a = buf1[w * 128 + j * 32 + l];
        v[4*j+0] = a.x; v[4*j+1] = a.y; v[4*j+2] = a.z; v[4*j+3] = a.w;
    }
    BUTTERFLY_ALL();

    // Exchange 1 into buf0 (free now)
    #pragma unroll
    for (int j = 0; j < 4; j++) {
        int s  = w * 128 + j * 32 + l;
        buf0[s ^ ((s >> 4) & 7)] =
            make_float4(v[4*j+0], v[4*j+1], v[4*j+2], v[4*j+3]);
    }
    __syncthreads();

    // Round 2
    #pragma unroll
    for (int i = 0; i < RPT; i++) v[i] = sf[((sbase + i) ^ sig) * 4 + p];
    BUTTERFLY_ALL();
    #pragma unroll
    for (int i = 0; i < RPT; i++) sf[((sbase + i) ^ sig) * 4 + p] = v[i];
    __syncthreads();

    // Round 3; store row B
    #pragma unroll
    for (int i2 = 0; i2 < RPT; i2++) {
        int b6 = i2 & 1, hi = i2 >> 1;
        int s  = mq + 16 * b6 + 32 * u2 + 128 * hi;
        v[i2] = sf[(s ^ (b6 + 2 * u2)) * 4 + mp];
    }
    BUTTERFLY_ALL();
    #pragma unroll
    for (int i2 = 0; i2 < RPT; i2++) {
        int b6 = i2 & 1, hi = i2 >> 1;
        __stcs(&y1[obase + 64 * b6 + 512 * hi], v[i2] * 0.015625f);
    }
}

extern "C" void kernel_launch(void* const* d_in, const int* in_sizes, int n_in,
                              void* d_out, int out_size)
{
    const float* X = (const float*)d_in[0];   // [8192, 4096] fp32
    // d_in[1]: dense Hadamard matrix H — unused (FWHT).
    float* Y = (float*)d_out;

    const int rows = in_sizes[0] / HN;        // 8192
    fwht2r_kernel<<<rows / 2, NTHREADS>>>(X, Y);
}

// round 13
// speedup vs baseline: 1.4125x; 1.4125x over previous
#include <cuda_runtime.h>

// Fast Walsh-Hadamard Transform, N=4096 fp32, one row per 256-thread CTA.
// All 12 stages in registers across 3 rounds (best-known R8 structure):
//   round 1: bits {0,1,7,8}   lane-contiguous LDG.128 (split 2+2, stages
//                             interleaved to halve the front load burst)
//   round 2: bits {2,3,4,5}   swizzled smem exchange
//   round 3: bits {6,9,10,11} swizzled smem exchange; coalesced scalar STG
// XOR swizzle on float4 slots: s' = s ^ ((s>>4)&7) — all patterns conflict-free.
// Output scaled by 2^-6 (normalized Hadamard).
//
// R13: __launch_bounds__(256, 7) -> 36-reg target, 7 CTAs/SM (occ midpoint
//      between proven occ6@40regs and regressive occ8@32regs). Split loads
//      keep MLP_p1=2 to limit cross-CTA L1tex-queue spread at higher oe.
//      Stores __stcs (write-once output, evict-first).

#define HN       4096
#define NTHREADS 256
#define RPT      16

__global__ __launch_bounds__(NTHREADS, 7)
void fwht_kernel(const float* __restrict__ X, float* __restrict__ Y)
{
    __shared__ float4 s4[HN / 4];              // 16 KB
    float* const sf = reinterpret_cast<float*>(s4);

    const size_t row = blockIdx.x;
    const float* __restrict__ x = X + row * HN;
    float*       __restrict__ y = Y + row * HN;

    const int t = threadIdx.x;
    const int w = t >> 5;          // warp 0..7
    const int l = t & 31;          // lane

    float v[RPT];

    // ---- Round 1: reg r = j*4+k maps to n-bits r0,r1 = n0,n1 ; r2,r3 = n7,n8
    // Split loads 2+2 with bit-0/1 stages interleaved (legal: the two halves
    // only interact at the st=4/8 stages).
    {
        const float4* __restrict__ xv = reinterpret_cast<const float4*>(x);
        #pragma unroll
        for (int j = 0; j < 2; j++) {
            float4 a = xv[w * 128 + j * 32 + l];
            v[4*j+0] = a.x; v[4*j+1] = a.y; v[4*j+2] = a.z; v[4*j+3] = a.w;
        }
        #pragma unroll
        for (int st = 1; st <= 2; st <<= 1) {
            #pragma unroll
            for (int i = 0; i < 8; i++) {
                if (!(i & st)) {
                    float a = v[i], b = v[i ^ st];
                    v[i] = a + b;  v[i ^ st] = a - b;
                }
            }
        }
        #pragma unroll
        for (int j = 2; j < 4; j++) {
            float4 a = xv[w * 128 + j * 32 + l];
            v[4*j+0] = a.x; v[4*j+1] = a.y; v[4*j+2] = a.z; v[4*j+3] = a.w;
        }
        #pragma unroll
        for (int st = 1; st <= 2; st <<= 1) {
            #pragma unroll
            for (int i = 8; i < 16; i++) {
                if (!(i & st)) {
                    float a = v[i], b = v[i ^ st];
                    v[i] = a + b;  v[i ^ st] = a - b;
                }
            }
        }
        // stages st=4 (n7), st=8 (n8) across all regs
        #pragma unroll
        for (int st = 4; st < RPT; st <<= 1) {
            #pragma unroll
            for (int i = 0; i < RPT; i++) {
                if (!(i & st)) {
                    float a = v[i], b = v[i ^ st];
                    v[i] = a + b;  v[i ^ st] = a - b;
                }
            }
        }
    }

    // ---- Exchange 1 write: float4 slot s = w*128 + j*32 + l, swizzled ----
    #pragma unroll
    for (int j = 0; j < 4; j++) {
        int s  = w * 128 + j * 32 + l;
        int ss = s ^ ((s >> 4) & 7);
        s4[ss] = make_float4(v[4*j+0], v[4*j+1], v[4*j+2], v[4*j+3]);
    }
    __syncthreads();

    // ---- Round 2: thread fixes p=n0n1, q=n6, u=n7n8, w=n9..11; i = n2..5 ----
    const int p  = l & 3;
    const int q  = (l >> 2) & 1;
    const int u  = (l >> 3) & 3;
    const int sbase = 16 * q + 32 * u + 128 * w;
    const int sig   = q + 2 * u;                   // = ((s>>4)&7) for these slots
    #pragma unroll
    for (int i = 0; i < RPT; i++) {
        int ss = (sbase + i) ^ sig;
        v[i] = sf[ss * 4 + p];
    }
    #pragma unroll
    for (int st = 1; st < RPT; st <<= 1) {
        #pragma unroll
        for (int i = 0; i < RPT; i++) {
            if (!(i & st)) {
                float a = v[i], b = v[i ^ st];
                v[i] = a + b;  v[i ^ st] = a - b;
            }
        }
    }
    // write back to the same (thread-private) addresses — no barrier needed first
    #pragma unroll
    for (int i = 0; i < RPT; i++) {
        int ss = (sbase + i) ^ sig;
        sf[ss * 4 + p] = v[i];
    }
    __syncthreads();

    // ---- Round 3: thread fixes m = n0..5, u2 = n7n8 ; i2 -> {n6, n9..11} ----
    const int u2 = w >> 1;                 // n7,n8
    const int m  = ((w & 1) << 5) | l;     // n0..5
    const int mq = m >> 2;
    const int mp = m & 3;
    #pragma unroll
    for (int i2 = 0; i2 < RPT; i2++) {
        int b6 = i2 & 1, hi = i2 >> 1;
        int s  = mq + 16 * b6 + 32 * u2 + 128 * hi;
        int sg = b6 + 2 * u2;              // = ((s>>4)&7)
        v[i2] = sf[(s ^ sg) * 4 + mp];
    }
    #pragma unroll
    for (int st = 1; st < RPT; st <<= 1) {
        #pragma unroll
        for (int i = 0; i < RPT; i++) {
            if (!(i & st)) {
                float a = v[i], b = v[i ^ st];
                v[i] = a + b;  v[i ^ st] = a - b;
            }
        }
    }

    // ---- Store: n = m + 64*b6 + 128*u2 + 512*hi ; lanes contiguous 128B ----
    const int obase = m + 128 * u2;
    #pragma unroll
    for (int i2 = 0; i2 < RPT; i2++) {
        int b6 = i2 & 1, hi = i2 >> 1;
        __stcs(&y[obase + 64 * b6 + 512 * hi], v[i2] * 0.015625f);   // * 2^-6
    }
}

extern "C" void kernel_launch(void* const* d_in, const int* in_sizes, int n_in,
                              void* d_out, int out_size)
{
    const float* X = (const float*)d_in[0];   // [8192, 4096] fp32
    // d_in[1]: dense Hadamard matrix H — unused (FWHT).
    float* Y = (float*)d_out;

    const int rows = in_sizes[0] / HN;        // 8192
    fwht_kernel<<<rows, NTHREADS>>>(X, Y);
}